// round 10
// baseline (speedup 1.0000x reference)
#include <cuda_runtime.h>
#include <cuda_bf16.h>
#include <cstdint>

#define BATCH 8
#define HIMG 80
#define WIMG 80
#define CDIM 768
#define NPOS (HIMG * WIMG)        // 6400
#define CQKV (3 * CDIM)           // 2304
#define WIN 14
#define NWIN 6
#define NHEAD 12
#define HD 64
#define NWP (WIN * WIN)           // 196
#define MROWS (BATCH * NPOS)      // 51200

// ---------------- scratch (__device__ globals: allocation-free rule) -------
__device__ float g_qkv[(size_t)MROWS * CQKV];
__device__ __nv_bfloat16 g_ahi[(size_t)MROWS * CDIM];
__device__ __nv_bfloat16 g_alo[(size_t)MROWS * CDIM];
__device__ __nv_bfloat16 g_bhi[(size_t)CQKV * CDIM];
__device__ __nv_bfloat16 g_blo[(size_t)CQKV * CDIM];

// ---------------- PTX helpers (no 'a'-suffix features) ---------------------
__device__ __forceinline__ uint32_t smem_u32(const void* p) {
    uint32_t a;
    asm("{ .reg .u64 t; cvta.to.shared.u64 t, %1; cvt.u32.u64 %0, t; }"
        : "=r"(a) : "l"(p));
    return a;
}
__device__ __forceinline__ void cp_async16(uint32_t dst, const void* src) {
    asm volatile("cp.async.cg.shared.global [%0], [%1], 16;"
                 :: "r"(dst), "l"(src));
}
#define CP_COMMIT() asm volatile("cp.async.commit_group;" ::: "memory")
#define CP_WAIT(n)  asm volatile("cp.async.wait_group %0;" :: "n"(n) : "memory")

__device__ __forceinline__ void ldm_x4(uint32_t* r, uint32_t addr) {
    asm volatile("ldmatrix.sync.aligned.m8n8.x4.shared.b16 {%0,%1,%2,%3}, [%4];"
                 : "=r"(r[0]), "=r"(r[1]), "=r"(r[2]), "=r"(r[3]) : "r"(addr));
}
__device__ __forceinline__ void mma_bf16(float* d, const uint32_t* a,
                                         uint32_t b0, uint32_t b1) {
    asm volatile(
        "mma.sync.aligned.m16n8k16.row.col.f32.bf16.bf16.f32 "
        "{%0,%1,%2,%3}, {%4,%5,%6,%7}, {%8,%9}, {%0,%1,%2,%3};"
        : "+f"(d[0]), "+f"(d[1]), "+f"(d[2]), "+f"(d[3])
        : "r"(a[0]), "r"(a[1]), "r"(a[2]), "r"(a[3]), "r"(b0), "r"(b1));
}

// ---------------------------------------------------------------------------
// bf16x3 GEMM via mma.sync: C = Ah*Bh + Ah*Bl + Al*Bh (+bias), fp32 acc.
// 128x128 tile, BK=32, 3-stage cp.async ring, 256 thr, 2 CTA/SM.
// Inner loop is TERM-OUTER per mi: same-acc reuse distance = 4 MMAs.
// ---------------------------------------------------------------------------
#define BM 128
#define BN 128
#define BK 32
#define STAGES 3
#define TILE_B (BM * BK * 2)          // 8192
#define STAGE_B (4 * TILE_B)          // 32768
#define GEMM_SMEM (STAGES * STAGE_B)  // 98304

__global__ __launch_bounds__(256, 2) void gemm_mma_bf16x3(
    const __nv_bfloat16* __restrict__ Ah, const __nv_bfloat16* __restrict__ Al,
    const __nv_bfloat16* __restrict__ Bh, const __nv_bfloat16* __restrict__ Bl,
    const float* __restrict__ bias, float* __restrict__ C,
    int M, int N, int K)
{
    extern __shared__ char sm[];
    const uint32_t smb = smem_u32(sm);
    const int tid  = threadIdx.x;
    const int wid  = tid >> 5;
    const int lane = tid & 31;
    const int bm = blockIdx.y * BM;
    const int bn = blockIdx.x * BN;
    const int warp_m = (wid >> 2) * 64;
    const int warp_n = (wid & 3) * 32;

    const __nv_bfloat16* gA[2] = { Ah + (size_t)bm * K, Al + (size_t)bm * K };
    const __nv_bfloat16* gB[2] = { Bh + (size_t)bn * K, Bl + (size_t)bn * K };

    float acc[4][4][4];
#pragma unroll
    for (int i = 0; i < 4; i++)
#pragma unroll
        for (int j = 0; j < 4; j++)
#pragma unroll
            for (int k = 0; k < 4; k++) acc[i][j][k] = 0.f;

    const int nchunk = K / BK;

    auto load_chunk = [&](int c) {
        const uint32_t bufb = smb + (c % STAGES) * STAGE_B;
        const int k0 = c * BK;
#pragma unroll
        for (int t = 0; t < 4; t++) {
            const __nv_bfloat16* src = (t < 2 ? gA[t] : gB[t - 2]) + k0;
            const uint32_t dstb = bufb + t * TILE_B;
#pragma unroll
            for (int i = 0; i < 2; i++) {
                const int idx = i * 256 + tid;
                const int row = idx >> 2, cc = idx & 3;
                const uint32_t sw = row * 64 + ((cc ^ ((row >> 1) & 3)) << 4);
                cp_async16(dstb + sw, src + (size_t)row * K + cc * 8);
            }
        }
        CP_COMMIT();
    };

    load_chunk(0);
    load_chunk(1);

    const int lrow  = lane & 15;
    const int lhalf = lane >> 4;

    for (int c = 0; c < nchunk; c++) {
        if (c + 1 < nchunk) CP_WAIT(1);
        else                CP_WAIT(0);
        __syncthreads();
        if (c + 2 < nchunk) load_chunk(c + 2);

        const uint32_t aHb = smb + (c % STAGES) * STAGE_B;
        const uint32_t aLb = aHb + TILE_B;
        const uint32_t bHb = aHb + 2 * TILE_B;
        const uint32_t bLb = aHb + 3 * TILE_B;

#pragma unroll
        for (int ks = 0; ks < 2; ks++) {
            const int ccol = ks * 2 + lhalf;
            uint32_t bh[2][4], bl[2][4];
#pragma unroll
            for (int j = 0; j < 2; j++) {
                const int row = warp_n + j * 16 + lrow;
                const uint32_t off = row * 64 + ((ccol ^ ((row >> 1) & 3)) << 4);
                ldm_x4(bh[j], bHb + off);
                ldm_x4(bl[j], bLb + off);
            }
#pragma unroll
            for (int mi = 0; mi < 4; mi++) {
                const int row = warp_m + mi * 16 + lrow;
                const uint32_t off = row * 64 + ((ccol ^ ((row >> 1) & 3)) << 4);
                uint32_t ah[4], al[4];
                ldm_x4(ah, aHb + off);
                ldm_x4(al, aLb + off);
                // term-outer: 4 independent accs between same-acc reuses
#pragma unroll
                for (int nj = 0; nj < 4; nj++) {
                    const int p = nj >> 1, s = nj & 1;
                    mma_bf16(acc[mi][nj], ah, bh[p][s], bh[p][s + 2]);
                }
#pragma unroll
                for (int nj = 0; nj < 4; nj++) {
                    const int p = nj >> 1, s = nj & 1;
                    mma_bf16(acc[mi][nj], ah, bl[p][s], bl[p][s + 2]);
                }
#pragma unroll
                for (int nj = 0; nj < 4; nj++) {
                    const int p = nj >> 1, s = nj & 1;
                    mma_bf16(acc[mi][nj], al, bh[p][s], bh[p][s + 2]);
                }
            }
        }
        __syncthreads();
    }

    const int row_t = lane >> 2;
    const int col_t = (lane & 3) * 2;
#pragma unroll
    for (int mi = 0; mi < 4; mi++) {
#pragma unroll
        for (int r = 0; r < 2; r++) {
            const int row = bm + warp_m + mi * 16 + row_t + r * 8;
            float* crow = C + (size_t)row * N + bn;
#pragma unroll
            for (int nj = 0; nj < 4; nj++) {
                const int col = warp_n + nj * 8 + col_t;
                float2 v;
                v.x = acc[mi][nj][r * 2 + 0];
                v.y = acc[mi][nj][r * 2 + 1];
                if (bias) { v.x += bias[bn + col]; v.y += bias[bn + col + 1]; }
                *(float2*)(crow + col) = v;
            }
        }
    }
}

// ---------------------------------------------------------------------------
// fp32 -> bf16 hi/lo splits
// ---------------------------------------------------------------------------
__global__ __launch_bounds__(256) void split_rm(
    const float* __restrict__ in, __nv_bfloat16* __restrict__ hi,
    __nv_bfloat16* __restrict__ lo, int n4)
{
    int i = blockIdx.x * blockDim.x + threadIdx.x;
    if (i < n4) {
        float4 v = ((const float4*)in)[i];
        float f[4] = { v.x, v.y, v.z, v.w };
        __nv_bfloat16 h[4], l[4];
#pragma unroll
        for (int j = 0; j < 4; j++) {
            h[j] = __float2bfloat16_rn(f[j]);
            l[j] = __float2bfloat16_rn(f[j] - __bfloat162float(h[j]));
        }
        ((ushort4*)hi)[i] = make_ushort4(
            __bfloat16_as_ushort(h[0]), __bfloat16_as_ushort(h[1]),
            __bfloat16_as_ushort(h[2]), __bfloat16_as_ushort(h[3]));
        ((ushort4*)lo)[i] = make_ushort4(
            __bfloat16_as_ushort(l[0]), __bfloat16_as_ushort(l[1]),
            __bfloat16_as_ushort(l[2]), __bfloat16_as_ushort(l[3]));
    }
}

__global__ __launch_bounds__(256) void split_tr(
    const float* __restrict__ W, __nv_bfloat16* __restrict__ hi,
    __nv_bfloat16* __restrict__ lo, int K, int N)
{
    int idx = blockIdx.x * blockDim.x + threadIdx.x;
    if (idx < K * N) {
        int n = idx / K, k = idx % K;
        float v = W[(size_t)k * N + n];
        __nv_bfloat16 h = __float2bfloat16_rn(v);
        hi[idx] = h;
        lo[idx] = __float2bfloat16_rn(v - __bfloat162float(h));
    }
}

// ---------------------------------------------------------------------------
// Windowed attention: 4 threads per query row (16 dims each), 800-thr blocks.
// Writes bf16 hi/lo output directly (feeds GEMM3, no split pass needed).
// ---------------------------------------------------------------------------
#define ATTN_THREADS 800

__global__ __launch_bounds__(ATTN_THREADS) void win_attn(
    const float* __restrict__ qkv,
    __nv_bfloat16* __restrict__ ohi, __nv_bfloat16* __restrict__ olo)
{
    const int idx  = blockIdx.x;
    const int head = idx % NHEAD;
    const int l    = (idx / NHEAD) % (NWIN * NWIN);
    const int b    = idx / (NHEAD * NWIN * NWIN);
    const int wi = l / NWIN, wj = l % NWIN;

    extern __shared__ float smf[];
    float* Ks = smf;               // [196][64]
    float* Vs = smf + NWP * HD;

    const int tid = threadIdx.x;

    for (int i = tid; i < NWP * (HD / 4); i += ATTN_THREADS) {
        const int p = i / (HD / 4);
        const int f = i % (HD / 4);
        const int r = p / WIN, c = p % WIN;
        const int h = wi * WIN + r, w = wj * WIN + c;
        float4 kv = make_float4(0.f, 0.f, 0.f, 0.f);
        float4 vv = make_float4(0.f, 0.f, 0.f, 0.f);
        if (h < HIMG && w < WIMG) {
            const size_t base =
                (size_t)(b * NPOS + h * WIMG + w) * CQKV + head * HD + f * 4;
            kv = *(const float4*)(qkv + base + CDIM);
            vv = *(const float4*)(qkv + base + 2 * CDIM);
        }
        ((float4*)Ks)[i] = kv;
        ((float4*)Vs)[i] = vv;
    }
    __syncthreads();

    // row = tid>>2, quad = tid&3 owns dims [quad*16, +16)
    const int row  = tid >> 2;          // 0..199
    const int quad = tid & 3;
    const int rcl = row < NWP ? row : NWP - 1;
    const int r = rcl / WIN, c = rcl % WIN;
    const int h = wi * WIN + r, w = wj * WIN + c;
    const bool valid = (row < NWP) && (h < HIMG) && (w < WIMG);
    const int hc = h < HIMG ? h : HIMG - 1;
    const int wc = w < WIMG ? w : WIMG - 1;

    const size_t qbase =
        (size_t)(b * NPOS + hc * WIMG + wc) * CQKV + head * HD + quad * 16;
    float4 q4[4];
#pragma unroll
    for (int d = 0; d < 4; d++)
        q4[d] = *(const float4*)(qkv + qbase + d * 4);

    float m = -1e30f, lsum = 0.f;
    float acc[16];
#pragma unroll
    for (int d = 0; d < 16; d++) acc[d] = 0.f;

    for (int j = 0; j < NWP; j++) {
        const float4* kj = (const float4*)(Ks + j * HD + quad * 16);
        float s0 = 0.f, s1 = 0.f, s2 = 0.f, s3 = 0.f;
#pragma unroll
        for (int d = 0; d < 4; d++) {
            float4 kv = kj[d];
            s0 = fmaf(q4[d].x, kv.x, s0);
            s1 = fmaf(q4[d].y, kv.y, s1);
            s2 = fmaf(q4[d].z, kv.z, s2);
            s3 = fmaf(q4[d].w, kv.w, s3);
        }
        float sh = (s0 + s1) + (s2 + s3);
        sh += __shfl_xor_sync(0xffffffffu, sh, 1);
        sh += __shfl_xor_sync(0xffffffffu, sh, 2);
        float s = sh * 0.125f;
        if (s > m) {
            const float corr = __expf(m - s);
            lsum *= corr;
#pragma unroll
            for (int d = 0; d < 16; d++) acc[d] *= corr;
            m = s;
        }
        const float p = __expf(s - m);
        lsum += p;
        const float4* vj = (const float4*)(Vs + j * HD + quad * 16);
#pragma unroll
        for (int d = 0; d < 4; d++) {
            float4 vv = vj[d];
            acc[d * 4 + 0] = fmaf(p, vv.x, acc[d * 4 + 0]);
            acc[d * 4 + 1] = fmaf(p, vv.y, acc[d * 4 + 1]);
            acc[d * 4 + 2] = fmaf(p, vv.z, acc[d * 4 + 2]);
            acc[d * 4 + 3] = fmaf(p, vv.w, acc[d * 4 + 3]);
        }
    }

    if (valid) {
        const float inv = 1.f / lsum;
        const size_t obase =
            (size_t)(b * NPOS + h * WIMG + w) * CDIM + head * HD + quad * 16;
        ushort hi16[16], lo16[16];
#pragma unroll
        for (int d = 0; d < 16; d++) {
            const float v = acc[d] * inv;
            const __nv_bfloat16 hh = __float2bfloat16_rn(v);
            hi16[d] = __bfloat16_as_ushort(hh);
            lo16[d] = __bfloat16_as_ushort(
                __float2bfloat16_rn(v - __bfloat162float(hh)));
        }
#pragma unroll
        for (int d = 0; d < 2; d++) {
            *(uint4*)(ohi + obase + d * 8) = ((const uint4*)hi16)[d];
            *(uint4*)(olo + obase + d * 8) = ((const uint4*)lo16)[d];
        }
    }
}

// ---------------------------------------------------------------------------
extern "C" void kernel_launch(void* const* d_in, const int* in_sizes, int n_in,
                              void* d_out, int out_size)
{
    const float* x     = (const float*)d_in[0];
    const float* Wqkv  = (const float*)d_in[1];
    const float* Wproj = (const float*)d_in[2];
    const float* bproj = (const float*)d_in[3];
    float* out = (float*)d_out;

    float *qkv;
    __nv_bfloat16 *ahi, *alo, *bhi, *blo;
    cudaGetSymbolAddress((void**)&qkv, g_qkv);
    cudaGetSymbolAddress((void**)&ahi, g_ahi);
    cudaGetSymbolAddress((void**)&alo, g_alo);
    cudaGetSymbolAddress((void**)&bhi, g_bhi);
    cudaGetSymbolAddress((void**)&blo, g_blo);

    cudaFuncSetAttribute(gemm_mma_bf16x3,
                         cudaFuncAttributeMaxDynamicSharedMemorySize, GEMM_SMEM);
    const int attn_smem = 2 * NWP * HD * (int)sizeof(float);
    cudaFuncSetAttribute(win_attn,
                         cudaFuncAttributeMaxDynamicSharedMemorySize, attn_smem);

    const int M = MROWS;

    // ---- GEMM1: qkv = x @ Wqkv ----
    {
        int n4 = M * CDIM / 4;
        split_rm<<<(n4 + 255) / 256, 256>>>(x, ahi, alo, n4);
        int ne = CDIM * CQKV;
        split_tr<<<(ne + 255) / 256, 256>>>(Wqkv, bhi, blo, CDIM, CQKV);
        dim3 grid(CQKV / BN, M / BM);
        gemm_mma_bf16x3<<<grid, 256, GEMM_SMEM>>>(
            ahi, alo, bhi, blo, nullptr, qkv, M, CQKV, CDIM);
    }

    // ---- windowed attention (writes bf16 hi/lo directly) ----
    {
        dim3 grid(BATCH * NWIN * NWIN * NHEAD);
        win_attn<<<grid, ATTN_THREADS, attn_smem>>>(qkv, ahi, alo);
    }

    // ---- GEMM3: out = att @ Wproj + bproj ----
    {
        int ne = CDIM * CDIM;
        split_tr<<<(ne + 255) / 256, 256>>>(Wproj, bhi, blo, CDIM, CDIM);
        dim3 grid(CDIM / BN, M / BM);
        gemm_mma_bf16x3<<<grid, 256, GEMM_SMEM>>>(
            ahi, alo, bhi, blo, bproj, out, M, CDIM, CDIM);
    }
}

// round 11
// speedup vs baseline: 1.3965x; 1.3965x over previous
#include <cuda_runtime.h>
#include <cuda_bf16.h>
#include <cstdint>

#define BATCH 8
#define HIMG 80
#define WIMG 80
#define CDIM 768
#define NPOS (HIMG * WIMG)        // 6400
#define CQKV (3 * CDIM)           // 2304
#define WIN 14
#define NWIN 6
#define NHEAD 12
#define HD 64
#define NWP (WIN * WIN)           // 196
#define MROWS (BATCH * NPOS)      // 51200

// ---------------- scratch (__device__ globals: allocation-free rule) -------
__device__ float g_qkv[(size_t)MROWS * CQKV];
__device__ __nv_bfloat16 g_ahi[(size_t)MROWS * CDIM];
__device__ __nv_bfloat16 g_alo[(size_t)MROWS * CDIM];
__device__ __nv_bfloat16 g_bhi[(size_t)CQKV * CDIM];
__device__ __nv_bfloat16 g_blo[(size_t)CQKV * CDIM];

// ---------------- PTX helpers (no 'a'-suffix features) ---------------------
__device__ __forceinline__ uint32_t smem_u32(const void* p) {
    uint32_t a;
    asm("{ .reg .u64 t; cvta.to.shared.u64 t, %1; cvt.u32.u64 %0, t; }"
        : "=r"(a) : "l"(p));
    return a;
}
__device__ __forceinline__ void cp_async16(uint32_t dst, const void* src) {
    asm volatile("cp.async.cg.shared.global [%0], [%1], 16;"
                 :: "r"(dst), "l"(src));
}
#define CP_COMMIT() asm volatile("cp.async.commit_group;" ::: "memory")
#define CP_WAIT(n)  asm volatile("cp.async.wait_group %0;" :: "n"(n) : "memory")

__device__ __forceinline__ void ldm_x4(uint32_t* r, uint32_t addr) {
    asm volatile("ldmatrix.sync.aligned.m8n8.x4.shared.b16 {%0,%1,%2,%3}, [%4];"
                 : "=r"(r[0]), "=r"(r[1]), "=r"(r[2]), "=r"(r[3]) : "r"(addr));
}
__device__ __forceinline__ void mma_bf16(float* d, const uint32_t* a,
                                         uint32_t b0, uint32_t b1) {
    asm volatile(
        "mma.sync.aligned.m16n8k16.row.col.f32.bf16.bf16.f32 "
        "{%0,%1,%2,%3}, {%4,%5,%6,%7}, {%8,%9}, {%0,%1,%2,%3};"
        : "+f"(d[0]), "+f"(d[1]), "+f"(d[2]), "+f"(d[3])
        : "r"(a[0]), "r"(a[1]), "r"(a[2]), "r"(a[3]), "r"(b0), "r"(b1));
}

// ---------------------------------------------------------------------------
// bf16x3 GEMM via mma.sync (R8 measured-best configuration).
// 128x128 tile, BK=32, 3-stage cp.async ring, 256 thr, 2 CTA/SM.
// ---------------------------------------------------------------------------
#define BM 128
#define BN 128
#define BK 32
#define STAGES 3
#define TILE_B (BM * BK * 2)          // 8192
#define STAGE_B (4 * TILE_B)          // 32768
#define GEMM_SMEM (STAGES * STAGE_B)  // 98304

__global__ __launch_bounds__(256, 2) void gemm_mma_bf16x3(
    const __nv_bfloat16* __restrict__ Ah, const __nv_bfloat16* __restrict__ Al,
    const __nv_bfloat16* __restrict__ Bh, const __nv_bfloat16* __restrict__ Bl,
    const float* __restrict__ bias, float* __restrict__ C,
    int M, int N, int K)
{
    extern __shared__ char sm[];
    const uint32_t smb = smem_u32(sm);
    const int tid  = threadIdx.x;
    const int wid  = tid >> 5;
    const int lane = tid & 31;
    const int bm = blockIdx.y * BM;
    const int bn = blockIdx.x * BN;
    const int warp_m = (wid >> 2) * 64;
    const int warp_n = (wid & 3) * 32;

    const __nv_bfloat16* gA[2] = { Ah + (size_t)bm * K, Al + (size_t)bm * K };
    const __nv_bfloat16* gB[2] = { Bh + (size_t)bn * K, Bl + (size_t)bn * K };

    float acc[4][4][4];
#pragma unroll
    for (int i = 0; i < 4; i++)
#pragma unroll
        for (int j = 0; j < 4; j++)
#pragma unroll
            for (int k = 0; k < 4; k++) acc[i][j][k] = 0.f;

    const int nchunk = K / BK;

    auto load_chunk = [&](int c) {
        const uint32_t bufb = smb + (c % STAGES) * STAGE_B;
        const int k0 = c * BK;
#pragma unroll
        for (int t = 0; t < 4; t++) {
            const __nv_bfloat16* src = (t < 2 ? gA[t] : gB[t - 2]) + k0;
            const uint32_t dstb = bufb + t * TILE_B;
#pragma unroll
            for (int i = 0; i < 2; i++) {
                const int idx = i * 256 + tid;
                const int row = idx >> 2, cc = idx & 3;
                const uint32_t sw = row * 64 + ((cc ^ ((row >> 1) & 3)) << 4);
                cp_async16(dstb + sw, src + (size_t)row * K + cc * 8);
            }
        }
        CP_COMMIT();
    };

    load_chunk(0);
    load_chunk(1);

    const int lrow  = lane & 15;
    const int lhalf = lane >> 4;

    for (int c = 0; c < nchunk; c++) {
        if (c + 1 < nchunk) CP_WAIT(1);
        else                CP_WAIT(0);
        __syncthreads();
        if (c + 2 < nchunk) load_chunk(c + 2);

        const uint32_t aHb = smb + (c % STAGES) * STAGE_B;
        const uint32_t aLb = aHb + TILE_B;
        const uint32_t bHb = aHb + 2 * TILE_B;
        const uint32_t bLb = aHb + 3 * TILE_B;

#pragma unroll
        for (int ks = 0; ks < 2; ks++) {
            const int ccol = ks * 2 + lhalf;
            uint32_t bh[2][4], bl[2][4];
#pragma unroll
            for (int j = 0; j < 2; j++) {
                const int row = warp_n + j * 16 + lrow;
                const uint32_t off = row * 64 + ((ccol ^ ((row >> 1) & 3)) << 4);
                ldm_x4(bh[j], bHb + off);
                ldm_x4(bl[j], bLb + off);
            }
#pragma unroll
            for (int mi = 0; mi < 4; mi++) {
                const int row = warp_m + mi * 16 + lrow;
                const uint32_t off = row * 64 + ((ccol ^ ((row >> 1) & 3)) << 4);
                uint32_t ah[4], al[4];
                ldm_x4(ah, aHb + off);
                ldm_x4(al, aLb + off);
#pragma unroll
                for (int nj = 0; nj < 4; nj++) {
                    const int p = nj >> 1, s = nj & 1;
                    mma_bf16(acc[mi][nj], ah, bh[p][s], bh[p][s + 2]);
                    mma_bf16(acc[mi][nj], ah, bl[p][s], bl[p][s + 2]);
                    mma_bf16(acc[mi][nj], al, bh[p][s], bh[p][s + 2]);
                }
            }
        }
        __syncthreads();
    }

    const int row_t = lane >> 2;
    const int col_t = (lane & 3) * 2;
#pragma unroll
    for (int mi = 0; mi < 4; mi++) {
#pragma unroll
        for (int r = 0; r < 2; r++) {
            const int row = bm + warp_m + mi * 16 + row_t + r * 8;
            float* crow = C + (size_t)row * N + bn;
#pragma unroll
            for (int nj = 0; nj < 4; nj++) {
                const int col = warp_n + nj * 8 + col_t;
                float2 v;
                v.x = acc[mi][nj][r * 2 + 0];
                v.y = acc[mi][nj][r * 2 + 1];
                if (bias) { v.x += bias[bn + col]; v.y += bias[bn + col + 1]; }
                *(float2*)(crow + col) = v;
            }
        }
    }
}

// ---------------------------------------------------------------------------
// fp32 -> bf16 hi/lo splits
// ---------------------------------------------------------------------------
__global__ __launch_bounds__(256) void split_rm(
    const float* __restrict__ in, __nv_bfloat16* __restrict__ hi,
    __nv_bfloat16* __restrict__ lo, int n4)
{
    int i = blockIdx.x * blockDim.x + threadIdx.x;
    if (i < n4) {
        float4 v = ((const float4*)in)[i];
        float f[4] = { v.x, v.y, v.z, v.w };
        __nv_bfloat16 h[4], l[4];
#pragma unroll
        for (int j = 0; j < 4; j++) {
            h[j] = __float2bfloat16_rn(f[j]);
            l[j] = __float2bfloat16_rn(f[j] - __bfloat162float(h[j]));
        }
        ((ushort4*)hi)[i] = make_ushort4(
            __bfloat16_as_ushort(h[0]), __bfloat16_as_ushort(h[1]),
            __bfloat16_as_ushort(h[2]), __bfloat16_as_ushort(h[3]));
        ((ushort4*)lo)[i] = make_ushort4(
            __bfloat16_as_ushort(l[0]), __bfloat16_as_ushort(l[1]),
            __bfloat16_as_ushort(l[2]), __bfloat16_as_ushort(l[3]));
    }
}

__global__ __launch_bounds__(256) void split_tr(
    const float* __restrict__ W, __nv_bfloat16* __restrict__ hi,
    __nv_bfloat16* __restrict__ lo, int K, int N)
{
    int idx = blockIdx.x * blockDim.x + threadIdx.x;
    if (idx < K * N) {
        int n = idx / K, k = idx % K;
        float v = W[(size_t)k * N + n];
        __nv_bfloat16 h = __float2bfloat16_rn(v);
        hi[idx] = h;
        lo[idx] = __float2bfloat16_rn(v - __bfloat162float(h));
    }
}

// ---------------------------------------------------------------------------
// Windowed attention: R8 thread-pair layout (2 thr/row, 32 dims each),
// j-loop unrolled by 2 for ILP; writes bf16 hi/lo output directly.
// ---------------------------------------------------------------------------
#define ATTN_THREADS 416

__global__ __launch_bounds__(ATTN_THREADS) void win_attn(
    const float* __restrict__ qkv,
    __nv_bfloat16* __restrict__ ohi, __nv_bfloat16* __restrict__ olo)
{
    const int idx  = blockIdx.x;
    const int head = idx % NHEAD;
    const int l    = (idx / NHEAD) % (NWIN * NWIN);
    const int b    = idx / (NHEAD * NWIN * NWIN);
    const int wi = l / NWIN, wj = l % NWIN;

    extern __shared__ float smf[];
    float* Ks = smf;               // [196][64]
    float* Vs = smf + NWP * HD;

    const int tid = threadIdx.x;

    for (int i = tid; i < NWP * (HD / 4); i += ATTN_THREADS) {
        const int p = i / (HD / 4);
        const int f = i % (HD / 4);
        const int r = p / WIN, c = p % WIN;
        const int h = wi * WIN + r, w = wj * WIN + c;
        float4 kv = make_float4(0.f, 0.f, 0.f, 0.f);
        float4 vv = make_float4(0.f, 0.f, 0.f, 0.f);
        if (h < HIMG && w < WIMG) {
            const size_t base =
                (size_t)(b * NPOS + h * WIMG + w) * CQKV + head * HD + f * 4;
            kv = *(const float4*)(qkv + base + CDIM);
            vv = *(const float4*)(qkv + base + 2 * CDIM);
        }
        ((float4*)Ks)[i] = kv;
        ((float4*)Vs)[i] = vv;
    }
    __syncthreads();

    // pair decomposition: row = tid>>1, half = tid&1 owns dims [half*32, +32)
    const int row  = tid >> 1;          // 0..207
    const int half = tid & 1;
    const int r = row / WIN, c = row % WIN;
    const int h = wi * WIN + r, w = wj * WIN + c;
    const bool valid = (row < NWP) && (h < HIMG) && (w < WIMG);
    const int hc = h < HIMG ? h : HIMG - 1;
    const int wc = w < WIMG ? w : WIMG - 1;

    const size_t qbase =
        (size_t)(b * NPOS + hc * WIMG + wc) * CQKV + head * HD + half * 32;
    float4 q4[8];
#pragma unroll
    for (int d = 0; d < 8; d++)
        q4[d] = *(const float4*)(qkv + qbase + d * 4);

    float m = -1e30f, lsum = 0.f;
    float acc[32];
#pragma unroll
    for (int d = 0; d < 32; d++) acc[d] = 0.f;

    // 196 keys, unrolled by 2: two independent dot chains per iteration,
    // one shared rescale test per pair.
    for (int j = 0; j < NWP; j += 2) {
        const float4* k0 = (const float4*)(Ks + j * HD + half * 32);
        const float4* k1 = (const float4*)(Ks + (j + 1) * HD + half * 32);
        float a0 = 0.f, a1 = 0.f, a2 = 0.f, a3 = 0.f;
        float b0 = 0.f, b1 = 0.f, b2 = 0.f, b3 = 0.f;
#pragma unroll
        for (int d = 0; d < 8; d++) {
            float4 ka = k0[d], kb = k1[d], qd = q4[d];
            a0 = fmaf(qd.x, ka.x, a0);
            a1 = fmaf(qd.y, ka.y, a1);
            a2 = fmaf(qd.z, ka.z, a2);
            a3 = fmaf(qd.w, ka.w, a3);
            b0 = fmaf(qd.x, kb.x, b0);
            b1 = fmaf(qd.y, kb.y, b1);
            b2 = fmaf(qd.z, kb.z, b2);
            b3 = fmaf(qd.w, kb.w, b3);
        }
        float sa = (a0 + a1) + (a2 + a3);
        float sb = (b0 + b1) + (b2 + b3);
        sa += __shfl_xor_sync(0xffffffffu, sa, 1);
        sb += __shfl_xor_sync(0xffffffffu, sb, 1);
        const float s0 = sa * 0.125f;
        const float s1 = sb * 0.125f;
        const float mx = fmaxf(s0, s1);
        if (mx > m) {
            const float corr = __expf(m - mx);
            lsum *= corr;
#pragma unroll
            for (int d = 0; d < 32; d++) acc[d] *= corr;
            m = mx;
        }
        const float p0 = __expf(s0 - m);
        const float p1 = __expf(s1 - m);
        lsum += p0 + p1;
        const float4* v0 = (const float4*)(Vs + j * HD + half * 32);
        const float4* v1 = (const float4*)(Vs + (j + 1) * HD + half * 32);
#pragma unroll
        for (int d = 0; d < 8; d++) {
            float4 va = v0[d], vb = v1[d];
            acc[d * 4 + 0] = fmaf(p0, va.x, fmaf(p1, vb.x, acc[d * 4 + 0]));
            acc[d * 4 + 1] = fmaf(p0, va.y, fmaf(p1, vb.y, acc[d * 4 + 1]));
            acc[d * 4 + 2] = fmaf(p0, va.z, fmaf(p1, vb.z, acc[d * 4 + 2]));
            acc[d * 4 + 3] = fmaf(p0, va.w, fmaf(p1, vb.w, acc[d * 4 + 3]));
        }
    }

    if (valid) {
        const float inv = 1.f / lsum;
        const size_t obase =
            (size_t)(b * NPOS + h * WIMG + w) * CDIM + head * HD + half * 32;
        ushort hi32[32], lo32[32];
#pragma unroll
        for (int d = 0; d < 32; d++) {
            const float v = acc[d] * inv;
            const __nv_bfloat16 hh = __float2bfloat16_rn(v);
            hi32[d] = __bfloat16_as_ushort(hh);
            lo32[d] = __bfloat16_as_ushort(
                __float2bfloat16_rn(v - __bfloat162float(hh)));
        }
#pragma unroll
        for (int d = 0; d < 4; d++) {
            *(uint4*)(ohi + obase + d * 8) = ((const uint4*)hi32)[d];
            *(uint4*)(olo + obase + d * 8) = ((const uint4*)lo32)[d];
        }
    }
}

// ---------------------------------------------------------------------------
extern "C" void kernel_launch(void* const* d_in, const int* in_sizes, int n_in,
                              void* d_out, int out_size)
{
    const float* x     = (const float*)d_in[0];
    const float* Wqkv  = (const float*)d_in[1];
    const float* Wproj = (const float*)d_in[2];
    const float* bproj = (const float*)d_in[3];
    float* out = (float*)d_out;

    float *qkv;
    __nv_bfloat16 *ahi, *alo, *bhi, *blo;
    cudaGetSymbolAddress((void**)&qkv, g_qkv);
    cudaGetSymbolAddress((void**)&ahi, g_ahi);
    cudaGetSymbolAddress((void**)&alo, g_alo);
    cudaGetSymbolAddress((void**)&bhi, g_bhi);
    cudaGetSymbolAddress((void**)&blo, g_blo);

    cudaFuncSetAttribute(gemm_mma_bf16x3,
                         cudaFuncAttributeMaxDynamicSharedMemorySize, GEMM_SMEM);
    const int attn_smem = 2 * NWP * HD * (int)sizeof(float);
    cudaFuncSetAttribute(win_attn,
                         cudaFuncAttributeMaxDynamicSharedMemorySize, attn_smem);

    const int M = MROWS;

    // ---- GEMM1: qkv = x @ Wqkv ----
    {
        int n4 = M * CDIM / 4;
        split_rm<<<(n4 + 255) / 256, 256>>>(x, ahi, alo, n4);
        int ne = CDIM * CQKV;
        split_tr<<<(ne + 255) / 256, 256>>>(Wqkv, bhi, blo, CDIM, CQKV);
        dim3 grid(CQKV / BN, M / BM);
        gemm_mma_bf16x3<<<grid, 256, GEMM_SMEM>>>(
            ahi, alo, bhi, blo, nullptr, qkv, M, CQKV, CDIM);
    }

    // ---- windowed attention (writes bf16 hi/lo directly) ----
    {
        dim3 grid(BATCH * NWIN * NWIN * NHEAD);
        win_attn<<<grid, ATTN_THREADS, attn_smem>>>(qkv, ahi, alo);
    }

    // ---- GEMM3: out = att @ Wproj + bproj ----
    {
        int ne = CDIM * CDIM;
        split_tr<<<(ne + 255) / 256, 256>>>(Wproj, bhi, blo, CDIM, CDIM);
        dim3 grid(CDIM / BN, M / BM);
        gemm_mma_bf16x3<<<grid, 256, GEMM_SMEM>>>(
            ahi, alo, bhi, blo, bproj, out, M, CDIM, CDIM);
    }
}